// round 3
// baseline (speedup 1.0000x reference)
#include <cuda_runtime.h>
#include <cstdint>

#define BB    128
#define CC    16
#define TT    2048
#define HH    256
#define NOUT  10
#define NBLK  128
#define NTHR  128
#define KP    136     // k-pairs: 128 (h) + 8 (x)
#define KHALF 68
#define HT_P  18      // ht row pitch (ulonglong)
#define WP_P  66      // wp row pitch (ulonglong)

static const int SMEM_BYTES = (KP * WP_P + KP * HT_P) * 8 + (2048 + 256 + 64) * 4; // 100864

// ---- persistent device state (no allocations allowed) ----
__device__ float g_xt[TT * BB * CC];          // x transposed to [t][b*c]
__device__ float g_h[2][BB * HH];             // h double buffer
__device__ unsigned g_arrive;
__device__ volatile unsigned g_release;

__device__ __forceinline__ unsigned long long ffma2(unsigned long long a,
                                                    unsigned long long b,
                                                    unsigned long long c) {
    unsigned long long d;
    asm("fma.rn.f32x2 %0, %1, %2, %3;" : "=l"(d) : "l"(a), "l"(b), "l"(c));
    return d;
}
__device__ __forceinline__ float lo32(unsigned long long v) {
    return __uint_as_float((unsigned)(v & 0xffffffffu));
}
__device__ __forceinline__ float hi32(unsigned long long v) {
    return __uint_as_float((unsigned)(v >> 32));
}
__device__ __forceinline__ float sigf(float x) { return 1.f / (1.f + __expf(-x)); }

// ---------------- init: zero h buffer 0, reset barrier ----------------
__global__ void init_kernel() {
    int i = blockIdx.x * blockDim.x + threadIdx.x;
    if (i < BB * HH) g_h[0][i] = 0.f;
    if (i == 0) { g_arrive = 0u; g_release = 0u; }
}

// ---------------- transpose x: (b*c, T) -> (t, b*c) ----------------
__global__ void trans_kernel(const float* __restrict__ x) {
    __shared__ float tile[32][33];
    const int t0 = blockIdx.x * 32, r0 = blockIdx.y * 32;
    const int tx = threadIdx.x, ty = threadIdx.y;  // 32 x 8
#pragma unroll
    for (int i = 0; i < 32; i += 8)
        tile[ty + i][tx] = x[(size_t)(r0 + ty + i) * TT + t0 + tx];
    __syncthreads();
#pragma unroll
    for (int i = 0; i < 32; i += 8)
        g_xt[(size_t)(t0 + ty + i) * (BB * CC) + r0 + tx] = tile[tx][ty + i];
}

// ---------------- persistent LSTM ----------------
__global__ void __launch_bounds__(NTHR, 1) lstm_kernel(
    const float* __restrict__ w_ih, const float* __restrict__ w_hh,
    const float* __restrict__ b_ih, const float* __restrict__ b_hh)
{
    extern __shared__ unsigned long long sm[];
    unsigned long long* wp = sm;                       // [KP][WP_P] k-paired W tile
    unsigned long long* ht = wp + KP * WP_P;           // [KP][HT_P] k-paired [kp][b]
    float* gpart = (float*)(ht + KP * HT_P);           // [2][16][64] k-half partials
    float* csm   = gpart + 2048;                       // [256] cell state
    float* bias  = csm + 256;                          // [64]

    const int tid = threadIdx.x;
    const int bid = blockIdx.x;
    const int bt  = bid >> 4;        // 8 batch tiles
    const int ut  = bid & 15;        // 16 unit tiles
    const int b0  = bt * 16;
    const int u0  = ut * 16;

    // ---- load W tile (once): local gate row g in [0,64): (gate, unit) ----
    for (int q = tid; q < KP * 64; q += NTHR) {
        const int g = q & 63, kp = q >> 6;
        const int grow = (g >> 4) * HH + u0 + (g & 15);
        unsigned long long v;
        if (kp < 128) v = *(const unsigned long long*)(w_hh + (size_t)grow * HH + 2 * kp);
        else          v = *(const unsigned long long*)(w_ih + (size_t)grow * CC + 2 * (kp - 128));
        wp[kp * WP_P + g] = v;
    }
    if (tid < 64) {
        const int grow = (tid >> 4) * HH + u0 + (tid & 15);
        bias[tid] = b_ih[grow] + b_hh[grow];
    }
    csm[tid] = 0.f;
    csm[tid + 128] = 0.f;

    // ---- GEMM thread mapping: warp = (khalf, ghalf), thread = 4b x 4g ----
    const int lane  = tid & 31;
    const int wrp   = tid >> 5;
    const int khalf = wrp >> 1;
    const int ghalf = wrp & 1;
    const int bs    = (lane & 3) * 4;                       // 4 b's: bs..bs+3
    const int g0    = ghalf * 32 + ((lane >> 2) & 7) * 4;   // 4 g's: g0..g0+3
    const int kp0   = khalf * KHALF;

    for (int s = 0; s < TT; ++s) {
        // ---- stage h_prev (transposed, k-paired) ----
        if (s == 0) {
#pragma unroll 4
            for (int q = tid; q < 128 * 16; q += NTHR) {
                const int kp = q & 127, b = q >> 7;
                ht[kp * HT_P + b] = 0ull;
            }
        } else {
            const float* hsrc = g_h[s & 1];
#pragma unroll 4
            for (int q = tid; q < 128 * 16; q += NTHR) {
                const int kp = q & 127, b = q >> 7;
                unsigned long long v =
                    __ldcg((const unsigned long long*)(hsrc + (size_t)(b0 + b) * HH + 2 * kp));
                ht[kp * HT_P + b] = v;
            }
        }
        // ---- stage x_t as kp 128..135 ----
        {
            const float* xsrc = g_xt + (size_t)s * (BB * CC);
            const int c2 = tid & 7, b = tid >> 3;
            unsigned long long v =
                *(const unsigned long long*)(xsrc + (b0 + b) * CC + 2 * c2);
            ht[(128 + c2) * HT_P + b] = v;
        }
        __syncthreads();

        // ---- GEMM: 4b x 4g x 68 k-pairs, packed f32x2 ----
        unsigned long long acc00 = 0, acc01 = 0, acc02 = 0, acc03 = 0;
        unsigned long long acc10 = 0, acc11 = 0, acc12 = 0, acc13 = 0;
        unsigned long long acc20 = 0, acc21 = 0, acc22 = 0, acc23 = 0;
        unsigned long long acc30 = 0, acc31 = 0, acc32 = 0, acc33 = 0;
        const unsigned long long* hp = ht + (size_t)kp0 * HT_P + bs;
        const unsigned long long* wq = wp + (size_t)kp0 * WP_P + g0;
#pragma unroll 4
        for (int kp = 0; kp < KHALF; ++kp) {
            const ulonglong2 hA = *(const ulonglong2*)(hp);
            const ulonglong2 hB = *(const ulonglong2*)(hp + 2);
            const ulonglong2 wA = *(const ulonglong2*)(wq);
            const ulonglong2 wB = *(const ulonglong2*)(wq + 2);
            acc00 = ffma2(hA.x, wA.x, acc00); acc01 = ffma2(hA.x, wA.y, acc01);
            acc02 = ffma2(hA.x, wB.x, acc02); acc03 = ffma2(hA.x, wB.y, acc03);
            acc10 = ffma2(hA.y, wA.x, acc10); acc11 = ffma2(hA.y, wA.y, acc11);
            acc12 = ffma2(hA.y, wB.x, acc12); acc13 = ffma2(hA.y, wB.y, acc13);
            acc20 = ffma2(hB.x, wA.x, acc20); acc21 = ffma2(hB.x, wA.y, acc21);
            acc22 = ffma2(hB.x, wB.x, acc22); acc23 = ffma2(hB.x, wB.y, acc23);
            acc30 = ffma2(hB.y, wA.x, acc30); acc31 = ffma2(hB.y, wA.y, acc31);
            acc32 = ffma2(hB.y, wB.x, acc32); acc33 = ffma2(hB.y, wB.y, acc33);
            hp += HT_P;
            wq += WP_P;
        }
        {
            float* gp = gpart + khalf * 1024 + bs * 64 + g0;
            gp[0]  = lo32(acc00) + hi32(acc00); gp[1]  = lo32(acc01) + hi32(acc01);
            gp[2]  = lo32(acc02) + hi32(acc02); gp[3]  = lo32(acc03) + hi32(acc03);
            gp += 64;
            gp[0]  = lo32(acc10) + hi32(acc10); gp[1]  = lo32(acc11) + hi32(acc11);
            gp[2]  = lo32(acc12) + hi32(acc12); gp[3]  = lo32(acc13) + hi32(acc13);
            gp += 64;
            gp[0]  = lo32(acc20) + hi32(acc20); gp[1]  = lo32(acc21) + hi32(acc21);
            gp[2]  = lo32(acc22) + hi32(acc22); gp[3]  = lo32(acc23) + hi32(acc23);
            gp += 64;
            gp[0]  = lo32(acc30) + hi32(acc30); gp[1]  = lo32(acc31) + hi32(acc31);
            gp[2]  = lo32(acc32) + hi32(acc32); gp[3]  = lo32(acc33) + hi32(acc33);
        }
        __syncthreads();

        // ---- pointwise LSTM update: 2 (b,unit) pairs per thread ----
        float* hdst = g_h[(s + 1) & 1];
#pragma unroll
        for (int r = 0; r < 2; ++r) {
            const int p = tid + r * 128;
            const int b = p >> 4, ui = p & 15;
            const float* gp = gpart + b * 64;
            const float iv = gp[ui]      + gp[1024 + ui]      + bias[ui];
            const float fv = gp[16 + ui] + gp[1024 + 16 + ui] + bias[16 + ui];
            const float gv = gp[32 + ui] + gp[1024 + 32 + ui] + bias[32 + ui];
            const float ov = gp[48 + ui] + gp[1024 + 48 + ui] + bias[48 + ui];
            const float ig = sigf(iv), fg = sigf(fv);
            const float gg = tanhf(gv), og = sigf(ov);
            const float c = fg * csm[p] + ig * gg;
            csm[p] = c;
            hdst[(size_t)(b0 + b) * HH + u0 + ui] = og * tanhf(c);
        }

        // ---- grid barrier (monotonic counter + release flag) ----
        __syncthreads();
        if (tid == 0) {
            __threadfence();
            const unsigned old = atomicAdd(&g_arrive, 1u);
            if (old == (unsigned)(NBLK * (s + 1) - 1)) {
                __threadfence();
                g_release = (unsigned)(s + 1);
            } else {
                while (g_release < (unsigned)(s + 1)) { }
            }
            __threadfence();
        }
        __syncthreads();
    }
}

// ---------------- classifier + log_softmax ----------------
__global__ void head_kernel(const float* __restrict__ w_out,
                            const float* __restrict__ b_out,
                            float* __restrict__ out)
{
    __shared__ float ws[NOUT * HH];
    __shared__ float bsm[NOUT];
    const int tid = threadIdx.x;
    for (int q = tid; q < NOUT * HH; q += NTHR) ws[q] = w_out[q];
    if (tid < NOUT) bsm[tid] = b_out[tid];
    __syncthreads();

    const float* hr = g_h[0] + (size_t)tid * HH;  // final h in buffer 0 (T even)
    float acc[NOUT];
#pragma unroll
    for (int j = 0; j < NOUT; ++j) acc[j] = bsm[j];
#pragma unroll 4
    for (int k = 0; k < HH; ++k) {
        const float hv = hr[k];
#pragma unroll
        for (int j = 0; j < NOUT; ++j) acc[j] += hv * ws[j * HH + k];
    }
    float m = acc[0];
#pragma unroll
    for (int j = 1; j < NOUT; ++j) m = fmaxf(m, acc[j]);
    float sum = 0.f;
#pragma unroll
    for (int j = 0; j < NOUT; ++j) sum += expf(acc[j] - m);
    const float lse = m + logf(sum);
#pragma unroll
    for (int j = 0; j < NOUT; ++j) out[tid * NOUT + j] = acc[j] - lse;
}

extern "C" void kernel_launch(void* const* d_in, const int* in_sizes, int n_in,
                              void* d_out, int out_size) {
    const float* x     = (const float*)d_in[0];
    const float* w_ih  = (const float*)d_in[1];
    const float* w_hh  = (const float*)d_in[2];
    const float* b_ih  = (const float*)d_in[3];
    const float* b_hh  = (const float*)d_in[4];
    const float* w_out = (const float*)d_in[5];
    const float* b_out = (const float*)d_in[6];
    float* out = (float*)d_out;

    cudaFuncSetAttribute(lstm_kernel, cudaFuncAttributeMaxDynamicSharedMemorySize, SMEM_BYTES);

    init_kernel<<<(BB * HH + 255) / 256, 256>>>();
    trans_kernel<<<dim3(TT / 32, (BB * CC) / 32), dim3(32, 8)>>>(x);
    lstm_kernel<<<NBLK, NTHR, SMEM_BYTES>>>(w_ih, w_hh, b_ih, b_hh);
    head_kernel<<<1, NTHR>>>(w_out, b_out, out);
}

// round 6
// speedup vs baseline: 1.1756x; 1.1756x over previous
#include <cuda_runtime.h>
#include <cstdint>

#define BB    128
#define CC    16
#define TT    2048
#define HH    256
#define NOUT  10
#define NBLK  128
#define NTHR  256
#define KP    136     // k-pairs: 128 (h) + 8 (x)
#define KQ    34      // k-pairs per warp (136/4)
#define HT_P  18      // ht row pitch (ulonglong)
#define WP_P  66      // wp row pitch (ulonglong)

static const int SMEM_BYTES = (KP * WP_P + KP * HT_P) * 8 + (4096 + 256 + 64) * 4; // 109056

// ---- persistent device state (no allocations allowed) ----
__device__ float g_xt[TT * BB * CC];          // x transposed to [t][b*c]
__device__ float g_h[2][BB * HH];             // h double buffer
__device__ unsigned g_cnt[8 * 32];            // per-group arrival counters (128B stride)
__device__ volatile unsigned g_rel[8 * 32];   // per-group release words (128B stride)

__device__ __forceinline__ unsigned long long ffma2(unsigned long long a,
                                                    unsigned long long b,
                                                    unsigned long long c) {
    unsigned long long d;
    asm("fma.rn.f32x2 %0, %1, %2, %3;" : "=l"(d) : "l"(a), "l"(b), "l"(c));
    return d;
}
__device__ __forceinline__ float psum(unsigned long long v) {
    return __uint_as_float((unsigned)(v & 0xffffffffu)) +
           __uint_as_float((unsigned)(v >> 32));
}
__device__ __forceinline__ float sigf(float x) { return 1.f / (1.f + __expf(-x)); }

// ---------------- init: zero h buffer 0, reset barrier state ----------------
__global__ void init_kernel() {
    int i = blockIdx.x * blockDim.x + threadIdx.x;
    if (i < BB * HH) g_h[0][i] = 0.f;
    if (i < 8 * 32) { g_cnt[i] = 0u; g_rel[i] = 0u; }
}

// ---------------- transpose x: (b*c, T) -> (t, b*c) ----------------
__global__ void trans_kernel(const float* __restrict__ x) {
    __shared__ float tile[32][33];
    const int t0 = blockIdx.x * 32, r0 = blockIdx.y * 32;
    const int tx = threadIdx.x, ty = threadIdx.y;  // 32 x 8
#pragma unroll
    for (int i = 0; i < 32; i += 8)
        tile[ty + i][tx] = x[(size_t)(r0 + ty + i) * TT + t0 + tx];
    __syncthreads();
#pragma unroll
    for (int i = 0; i < 32; i += 8)
        g_xt[(size_t)(t0 + ty + i) * (BB * CC) + r0 + tx] = tile[tx][ty + i];
}

// ---------------- persistent LSTM ----------------
__global__ void __launch_bounds__(NTHR, 1) lstm_kernel(
    const float* __restrict__ w_ih, const float* __restrict__ w_hh,
    const float* __restrict__ b_ih, const float* __restrict__ b_hh)
{
    extern __shared__ unsigned long long sm[];
    unsigned long long* wp = sm;                       // [KP][WP_P] k-paired W tile
    unsigned long long* ht = wp + KP * WP_P;           // [KP][HT_P] k-paired [kp][b]
    float* gpart = (float*)(ht + KP * HT_P);           // [4][16][64] k-quarter partials
    float* csm   = gpart + 4096;                       // [256] cell state
    float* bias  = csm + 256;                          // [64]

    const int tid = threadIdx.x;
    const int bid = blockIdx.x;
    const int bt  = bid >> 4;        // 8 batch tiles (sync group)
    const int ut  = bid & 15;        // 16 unit tiles
    const int b0  = bt * 16;
    const int u0  = ut * 16;

    // ---- load W tile (once): local gate row g in [0,64): (gate, unit) ----
    for (int q = tid; q < KP * 64; q += NTHR) {
        const int g = q & 63, kp = q >> 6;
        const int grow = (g >> 4) * HH + u0 + (g & 15);
        unsigned long long v;
        if (kp < 128) v = *(const unsigned long long*)(w_hh + (size_t)grow * HH + 2 * kp);
        else          v = *(const unsigned long long*)(w_ih + (size_t)grow * CC + 2 * (kp - 128));
        wp[kp * WP_P + g] = v;
    }
    if (tid < 64) {
        const int grow = (tid >> 4) * HH + u0 + (tid & 15);
        bias[tid] = b_ih[grow] + b_hh[grow];
    }
    csm[tid] = 0.f;

    // ---- GEMM thread mapping: warp = (kquarter, ghalf), thread = 4b x 4g ----
    const int lane  = tid & 31;
    const int wrp   = tid >> 5;
    const int kq    = wrp >> 1;                             // 0..3
    const int ghalf = wrp & 1;
    const int bs    = (lane & 3) * 4;                       // 4 b's: bs..bs+3
    const int g0    = ghalf * 32 + ((lane >> 2) & 7) * 4;   // 4 g's: g0..g0+3
    const int kp0   = kq * KQ;

    for (int s = 0; s < TT; ++s) {
        // ---- stage x_t as kp 128..135 (issue long-latency loads first) ----
        if (tid < 128) {
            const float* xsrc = g_xt + (size_t)s * (BB * CC);
            const int c2 = tid & 7, b = tid >> 3;
            unsigned long long v =
                *(const unsigned long long*)(xsrc + (b0 + b) * CC + 2 * c2);
            ht[(128 + c2) * HT_P + b] = v;
        }
        // ---- stage h_prev (transposed, k-paired) ----
        if (s == 0) {
#pragma unroll
            for (int q = tid; q < 128 * 16; q += NTHR) {
                const int kp = q & 127, b = q >> 7;
                ht[kp * HT_P + b] = 0ull;
            }
        } else {
            const float* hsrc = g_h[s & 1];
#pragma unroll
            for (int q = tid; q < 128 * 16; q += NTHR) {
                const int kp = q & 127, b = q >> 7;
                unsigned long long v =
                    __ldcg((const unsigned long long*)(hsrc + (size_t)(b0 + b) * HH + 2 * kp));
                ht[kp * HT_P + b] = v;
            }
        }
        __syncthreads();

        // ---- GEMM: 4b x 4g x 34 k-pairs per warp, packed f32x2 ----
        unsigned long long acc00 = 0, acc01 = 0, acc02 = 0, acc03 = 0;
        unsigned long long acc10 = 0, acc11 = 0, acc12 = 0, acc13 = 0;
        unsigned long long acc20 = 0, acc21 = 0, acc22 = 0, acc23 = 0;
        unsigned long long acc30 = 0, acc31 = 0, acc32 = 0, acc33 = 0;
        const unsigned long long* hp = ht + (size_t)kp0 * HT_P + bs;
        const unsigned long long* wq = wp + (size_t)kp0 * WP_P + g0;
#pragma unroll 2
        for (int kp = 0; kp < KQ; ++kp) {
            const ulonglong2 hA = *(const ulonglong2*)(hp);
            const ulonglong2 hB = *(const ulonglong2*)(hp + 2);
            const ulonglong2 wA = *(const ulonglong2*)(wq);
            const ulonglong2 wB = *(const ulonglong2*)(wq + 2);
            acc00 = ffma2(hA.x, wA.x, acc00); acc01 = ffma2(hA.x, wA.y, acc01);
            acc02 = ffma2(hA.x, wB.x, acc02); acc03 = ffma2(hA.x, wB.y, acc03);
            acc10 = ffma2(hA.y, wA.x, acc10); acc11 = ffma2(hA.y, wA.y, acc11);
            acc12 = ffma2(hA.y, wB.x, acc12); acc13 = ffma2(hA.y, wB.y, acc13);
            acc20 = ffma2(hB.x, wA.x, acc20); acc21 = ffma2(hB.x, wA.y, acc21);
            acc22 = ffma2(hB.x, wB.x, acc22); acc23 = ffma2(hB.x, wB.y, acc23);
            acc30 = ffma2(hB.y, wA.x, acc30); acc31 = ffma2(hB.y, wA.y, acc31);
            acc32 = ffma2(hB.y, wB.x, acc32); acc33 = ffma2(hB.y, wB.y, acc33);
            hp += HT_P;
            wq += WP_P;
        }
        {
            float4* gp4 = (float4*)(gpart + kq * 1024 + bs * 64 + g0);
            gp4[0]  = make_float4(psum(acc00), psum(acc01), psum(acc02), psum(acc03));
            gp4[16] = make_float4(psum(acc10), psum(acc11), psum(acc12), psum(acc13));
            gp4[32] = make_float4(psum(acc20), psum(acc21), psum(acc22), psum(acc23));
            gp4[48] = make_float4(psum(acc30), psum(acc31), psum(acc32), psum(acc33));
        }
        __syncthreads();

        // ---- pointwise LSTM update: one (b,unit) per thread ----
        {
            float* hdst = g_h[(s + 1) & 1];
            const int b = tid >> 4, ui = tid & 15;
            const float* gp = gpart + b * 64 + ui;
            const float iv = gp[0]  + gp[1024]      + gp[2048]      + gp[3072]      + bias[ui];
            const float fv = gp[16] + gp[1024 + 16] + gp[2048 + 16] + gp[3072 + 16] + bias[16 + ui];
            const float gv = gp[32] + gp[1024 + 32] + gp[2048 + 32] + gp[3072 + 32] + bias[32 + ui];
            const float ov = gp[48] + gp[1024 + 48] + gp[2048 + 48] + gp[3072 + 48] + bias[48 + ui];
            const float ig = sigf(iv), fg = sigf(fv);
            const float gg = tanhf(gv), og = sigf(ov);
            const float c = fg * csm[tid] + ig * gg;
            csm[tid] = c;
            hdst[(size_t)(b0 + b) * HH + u0 + ui] = og * tanhf(c);
        }

        // ---- per-group barrier: atomic counter + volatile release (R2-proven) ----
        __syncthreads();
        if (tid == 0) {
            __threadfence();
            const unsigned old = atomicAdd(&g_cnt[bt * 32], 1u);
            if (old == (unsigned)(16 * (s + 1) - 1)) {
                __threadfence();
                g_rel[bt * 32] = (unsigned)(s + 1);
            } else {
                while (g_rel[bt * 32] < (unsigned)(s + 1)) { }
            }
            __threadfence();
        }
        __syncthreads();
    }
}

// ---------------- classifier + log_softmax ----------------
__global__ void head_kernel(const float* __restrict__ w_out,
                            const float* __restrict__ b_out,
                            float* __restrict__ out)
{
    __shared__ float4 ws[NOUT][64];   // w_out as float4 along H
    __shared__ float bsm[NOUT];
    const int tid = threadIdx.x;
    for (int q = tid; q < NOUT * 64; q += 128)
        ws[q / 64][q & 63] = ((const float4*)w_out)[q];
    if (tid < NOUT) bsm[tid] = b_out[tid];
    __syncthreads();

    const int b     = blockIdx.x * 16 + (tid >> 3);  // batch
    const int slice = tid & 7;                       // k-slice: 8 float4 each
    const float4* hr4 = (const float4*)(g_h[0] + (size_t)b * HH) + slice * 8;

    float acc[NOUT];
#pragma unroll
    for (int j = 0; j < NOUT; ++j) acc[j] = 0.f;
#pragma unroll
    for (int k4 = 0; k4 < 8; ++k4) {
        const float4 hv = hr4[k4];
#pragma unroll
        for (int j = 0; j < NOUT; ++j) {
            const float4 wv = ws[j][slice * 8 + k4];
            acc[j] += hv.x * wv.x + hv.y * wv.y + hv.z * wv.z + hv.w * wv.w;
        }
    }
#pragma unroll
    for (int off = 4; off > 0; off >>= 1)
#pragma unroll
        for (int j = 0; j < NOUT; ++j)
            acc[j] += __shfl_down_sync(0xffffffffu, acc[j], off, 8);

    if (slice == 0) {
#pragma unroll
        for (int j = 0; j < NOUT; ++j) acc[j] += bsm[j];
        float m = acc[0];
#pragma unroll
        for (int j = 1; j < NOUT; ++j) m = fmaxf(m, acc[j]);
        float sum = 0.f;
#pragma unroll
        for (int j = 0; j < NOUT; ++j) sum += expf(acc[j] - m);
        const float lse = m + logf(sum);
#pragma unroll
        for (int j = 0; j < NOUT; ++j) out[b * NOUT + j] = acc[j] - lse;
    }
}

extern "C" void kernel_launch(void* const* d_in, const int* in_sizes, int n_in,
                              void* d_out, int out_size) {
    const float* x     = (const float*)d_in[0];
    const float* w_ih  = (const float*)d_in[1];
    const float* w_hh  = (const float*)d_in[2];
    const float* b_ih  = (const float*)d_in[3];
    const float* b_hh  = (const float*)d_in[4];
    const float* w_out = (const float*)d_in[5];
    const float* b_out = (const float*)d_in[6];
    float* out = (float*)d_out;

    cudaFuncSetAttribute(lstm_kernel, cudaFuncAttributeMaxDynamicSharedMemorySize, SMEM_BYTES);

    init_kernel<<<(BB * HH + 255) / 256, 256>>>();
    trans_kernel<<<dim3(TT / 32, (BB * CC) / 32), dim3(32, 8)>>>(x);
    lstm_kernel<<<NBLK, NTHR, SMEM_BYTES>>>(w_ih, w_hh, b_ih, b_hh);
    head_kernel<<<8, 128>>>(w_out, b_out, out);
}